// round 5
// baseline (speedup 1.0000x reference)
#include <cuda_runtime.h>
#include <cstdint>

#define B_ 128
#define T_ 1024
#define I_ 512
#define H_ 1024
#define O_ 512
#define NCTA_REC 128   // 2 batch-halves x 64 column-slices; 1 CTA/SM -> all co-resident

// ---------------- scratch (device globals; keep total well under 2GB: nvcc emits
// host shadow symbols and an oversized .bss breaks the x86-64 link) ----------------
__device__ float g_RX[T_ * B_ * H_];  // [t][b][h] rx ; later LN output
__device__ float g_ZX[T_ * B_ * H_];  // [t][b][h] zx ; later skip projection
__device__ float g_NX[T_ * B_ * H_];  // [t][b][h] nx ; overwritten in-place with h_t
__device__ float g_H[2 * B_ * H_];    // ping-pong hidden state
__device__ volatile unsigned g_gen;   // grid barrier generation
__device__ unsigned g_count;          // grid barrier arrival counter

// ---------------- helpers ----------------
__device__ __forceinline__ unsigned f2tf32(float x) {
    unsigned r;
    asm("cvt.rna.tf32.f32 %0, %1;" : "=r"(r) : "f"(x));
    return r;
}

__device__ __forceinline__ void mma_tf32(float c[4], const unsigned a[4], const unsigned b[2]) {
    asm volatile(
        "mma.sync.aligned.m16n8k8.row.col.f32.tf32.tf32.f32 "
        "{%0,%1,%2,%3},{%4,%5,%6,%7},{%8,%9},{%0,%1,%2,%3};"
        : "+f"(c[0]), "+f"(c[1]), "+f"(c[2]), "+f"(c[3])
        : "r"(a[0]), "r"(a[1]), "r"(a[2]), "r"(a[3]), "r"(b[0]), "r"(b[1]));
}

__device__ __forceinline__ void grid_barrier() {
    __syncthreads();
    if (threadIdx.x == 0) {
        __threadfence();
        unsigned old = g_gen;
        if (atomicAdd(&g_count, 1) == NCTA_REC - 1) {
            g_count = 0;
            __threadfence();
            g_gen = old + 1;
        } else {
            while (g_gen == old) { __nanosleep(64); }
        }
    }
    __syncthreads();
}

// ---------------- generic TN GEMM:  C = A(MxK, row-major) * W(NxK, row-major)^T + bias ----------------
// A source: Aext if non-null, else g_RX.
// C dest (c_sel): 0=g_RX 1=g_ZX 2=g_NX 4=Cext.
// Output remap: element (m,n) -> C[ ((m % 2^p_shift) * Q + (m >> p_shift)) * ldo + n ]
__global__ __launch_bounds__(256) void gemm_tn_tf32(
    const float* __restrict__ Aext, const float* __restrict__ W,
    const float* __restrict__ bias, float* __restrict__ Cext,
    int c_sel, int K, int p_shift, int Q, int ldo)
{
    __shared__ unsigned As[128][36];
    __shared__ unsigned Bs[64][36];

    const float* A = Aext ? Aext : g_RX;
    float* Cout;
    switch (c_sel) {
        case 0: Cout = g_RX; break;
        case 1: Cout = g_ZX; break;
        case 2: Cout = g_NX; break;
        default: Cout = Cext; break;
    }

    const int tid  = threadIdx.x;
    const int m0   = blockIdx.y * 128;
    const int n0   = blockIdx.x * 64;
    const int warp = tid >> 5, lane = tid & 31;
    const int g    = lane >> 2, tig = lane & 3;
    const int wM   = warp & 3, wN = warp >> 2;

    float acc[2][4][4];
#pragma unroll
    for (int mt = 0; mt < 2; mt++)
#pragma unroll
        for (int nt = 0; nt < 4; nt++)
#pragma unroll
            for (int r = 0; r < 4; r++) acc[mt][nt][r] = 0.f;

    for (int kt = 0; kt < K; kt += 32) {
#pragma unroll
        for (int j = 0; j < 4; j++) {
            int f = tid + j * 256;
            int row = f >> 3, c4 = (f & 7) * 4;
            float4 v = *reinterpret_cast<const float4*>(&A[(size_t)(m0 + row) * K + kt + c4]);
            As[row][c4 + 0] = f2tf32(v.x); As[row][c4 + 1] = f2tf32(v.y);
            As[row][c4 + 2] = f2tf32(v.z); As[row][c4 + 3] = f2tf32(v.w);
        }
#pragma unroll
        for (int j = 0; j < 2; j++) {
            int f = tid + j * 256;
            int row = f >> 3, c4 = (f & 7) * 4;
            float4 v = *reinterpret_cast<const float4*>(&W[(size_t)(n0 + row) * K + kt + c4]);
            Bs[row][c4 + 0] = f2tf32(v.x); Bs[row][c4 + 1] = f2tf32(v.y);
            Bs[row][c4 + 2] = f2tf32(v.z); Bs[row][c4 + 3] = f2tf32(v.w);
        }
        __syncthreads();

#pragma unroll
        for (int ks = 0; ks < 4; ks++) {
            const int kk = ks * 8;
            unsigned af[2][4], bf[4][2];
#pragma unroll
            for (int mt = 0; mt < 2; mt++) {
                int r0 = wM * 32 + mt * 16 + g;
                af[mt][0] = As[r0][kk + tig];
                af[mt][1] = As[r0 + 8][kk + tig];
                af[mt][2] = As[r0][kk + tig + 4];
                af[mt][3] = As[r0 + 8][kk + tig + 4];
            }
#pragma unroll
            for (int nt = 0; nt < 4; nt++) {
                int r0 = wN * 32 + nt * 8 + g;
                bf[nt][0] = Bs[r0][kk + tig];
                bf[nt][1] = Bs[r0][kk + tig + 4];
            }
#pragma unroll
            for (int mt = 0; mt < 2; mt++)
#pragma unroll
                for (int nt = 0; nt < 4; nt++) mma_tf32(acc[mt][nt], af[mt], bf[nt]);
        }
        __syncthreads();
    }

    const int Pm1 = (1 << p_shift) - 1;
#pragma unroll
    for (int mt = 0; mt < 2; mt++)
#pragma unroll
        for (int nt = 0; nt < 4; nt++)
#pragma unroll
            for (int r = 0; r < 4; r++) {
                int row = m0 + wM * 32 + mt * 16 + g + ((r >> 1) << 3);
                int col = n0 + wN * 32 + nt * 8 + 2 * tig + (r & 1);
                size_t oidx = ((size_t)((row & Pm1) * Q + (row >> p_shift))) * ldo + col;
                Cout[oidx] = acc[mt][nt][r] + bias[col];
            }
}

// ---------------- persistent GRU recurrence ----------------
// Grid: 128 CTAs = (bhalf 0..1) x (64 column slices of 16). One launch for all T steps.
// Weights for this CTA's 16 cols x 3 gates live in SMEM for the whole kernel
// (tf32-preconverted, stride 1028 words -> conflict-free b-fragment reads).
// h staging (64 rows x 32 k) is double-buffered: 1 syncthreads per chunk.
#define WSTRIDE 1028
#define SMEM_REC_BYTES ((3 * 16 * WSTRIDE + 2 * 64 * 36) * 4)

__global__ __launch_bounds__(256) void gru_persistent(
    const float* __restrict__ Whr, const float* __restrict__ Whz, const float* __restrict__ Whn,
    const float* __restrict__ bhr, const float* __restrict__ bhz, const float* __restrict__ bhn)
{
    extern __shared__ unsigned smem[];
    unsigned* Wp  = smem;                       // [3][16][WSTRIDE]
    unsigned* Hsm = smem + 3 * 16 * WSTRIDE;    // [2][64][36]

    const int tid  = threadIdx.x, warp = tid >> 5, lane = tid & 31;
    const int g    = lane >> 2, tig = lane & 3;
    const int wM   = warp & 3, wN = warp >> 2;   // 4 m-warps x 2 n-warps
    const int bhalf = blockIdx.x >> 6;           // 0..1 (64 batch rows each)
    const int nbase = (blockIdx.x & 63) * 16;    // 16-column slice

    // one-time: stage this CTA's weight slice into SMEM (tf32)
    for (int idx = tid; idx < 3 * 16 * 256; idx += 256) {
        int q = idx >> 12;                 // / 4096
        int rem = idx & 4095;
        int c = rem >> 8;
        int k4 = (rem & 255) * 4;
        const float* wsrc = (q == 0) ? Whr : (q == 1) ? Whz : Whn;
        float4 v = *reinterpret_cast<const float4*>(&wsrc[(size_t)(nbase + c) * H_ + k4]);
        unsigned* d = Wp + (q * 16 + c) * WSTRIDE + k4;
        d[0] = f2tf32(v.x); d[1] = f2tf32(v.y); d[2] = f2tf32(v.z); d[3] = f2tf32(v.w);
    }
    __syncthreads();

    float b_r[4], b_z[4], b_n[4];
#pragma unroll
    for (int r = 0; r < 4; r++) {
        int col = nbase + wN * 8 + 2 * tig + (r & 1);
        b_r[r] = bhr[col]; b_z[r] = bhz[col]; b_n[r] = bhn[col];
    }

    for (int t = 0; t < T_; t++) {
        const float* h_in = g_H + (size_t)(t & 1) * (B_ * H_);
        float* h_out = g_H + (size_t)((t + 1) & 1) * (B_ * H_);

        float acc[3][4];
#pragma unroll
        for (int q = 0; q < 3; q++)
#pragma unroll
            for (int r = 0; r < 4; r++) acc[q][r] = 0.f;

        // stage chunk 0
#pragma unroll
        for (int j = 0; j < 2; j++) {
            int f = tid + j * 256;
            int row = f >> 3, c4 = (f & 7) * 4;
            float4 v = *reinterpret_cast<const float4*>(&h_in[(size_t)(bhalf * 64 + row) * H_ + c4]);
            unsigned* d = Hsm + row * 36 + c4;
            d[0] = f2tf32(v.x); d[1] = f2tf32(v.y); d[2] = f2tf32(v.z); d[3] = f2tf32(v.w);
        }
        __syncthreads();

        for (int cch = 0; cch < 32; cch++) {
            const int kt = cch * 32;
            const int cur = cch & 1;
            if (cch < 31) {
                const int nxt = (cch + 1) & 1;
                const int ktn = kt + 32;
#pragma unroll
                for (int j = 0; j < 2; j++) {
                    int f = tid + j * 256;
                    int row = f >> 3, c4 = (f & 7) * 4;
                    float4 v = *reinterpret_cast<const float4*>(&h_in[(size_t)(bhalf * 64 + row) * H_ + ktn + c4]);
                    unsigned* d = Hsm + (nxt * 64 + row) * 36 + c4;
                    d[0] = f2tf32(v.x); d[1] = f2tf32(v.y); d[2] = f2tf32(v.z); d[3] = f2tf32(v.w);
                }
            }
#pragma unroll
            for (int ks = 0; ks < 4; ks++) {
                const int kk = ks * 8;
                unsigned af[4];
                const int r0 = wM * 16 + g;
                const unsigned* hb = Hsm + cur * 64 * 36;
                af[0] = hb[(r0)     * 36 + kk + tig];
                af[1] = hb[(r0 + 8) * 36 + kk + tig];
                af[2] = hb[(r0)     * 36 + kk + tig + 4];
                af[3] = hb[(r0 + 8) * 36 + kk + tig + 4];
#pragma unroll
                for (int q = 0; q < 3; q++) {
                    const unsigned* wrow = Wp + (q * 16 + wN * 8 + g) * WSTRIDE + kt + kk;
                    unsigned bf[2] = {wrow[tig], wrow[tig + 4]};
                    mma_tf32(acc[q], af, bf);
                }
            }
            __syncthreads();
        }

        // epilogue: gates + h update; h_t overwrites g_NX[gi] (same-thread RAW)
#pragma unroll
        for (int r = 0; r < 4; r++) {
            int row = bhalf * 64 + wM * 16 + g + ((r >> 1) << 3);  // batch index
            int col = nbase + wN * 8 + 2 * tig + (r & 1);          // hidden index
            size_t gi = (size_t)t * (B_ * H_) + (size_t)row * H_ + col;
            float rp = acc[0][r] + b_r[r] + g_RX[gi];
            float zp = acc[1][r] + b_z[r] + g_ZX[gi];
            float rr = 1.f / (1.f + expf(-rp));
            float zz = 1.f / (1.f + expf(-zp));
            float nn = tanhf(g_NX[gi] + rr * (acc[2][r] + b_n[r]));
            float hp = h_in[(size_t)row * H_ + col];
            float hn = fmaf(zz, hp - nn, nn);
            h_out[(size_t)row * H_ + col] = hn;
            g_NX[gi] = hn;  // HS shares the NX buffer
        }

        grid_barrier();
    }
}

// ---------------- LayerNorm over H of (g_NX=hs + g_ZX=skip), writes into g_RX ----------------
__global__ __launch_bounds__(128) void ln_kernel(
    const float* __restrict__ gamma, const float* __restrict__ beta)
{
    __shared__ float red[8];
    const size_t base = (size_t)blockIdx.x * H_;
    const int tid = threadIdx.x;
    float v[8], s = 0.f, s2 = 0.f;
#pragma unroll
    for (int i = 0; i < 8; i++) {
        int idx = tid + i * 128;
        float c = g_NX[base + idx] + g_ZX[base + idx];
        v[i] = c; s += c; s2 += c * c;
    }
#pragma unroll
    for (int o = 16; o > 0; o >>= 1) {
        s += __shfl_xor_sync(0xFFFFFFFFu, s, o);
        s2 += __shfl_xor_sync(0xFFFFFFFFu, s2, o);
    }
    int warp = tid >> 5, lane = tid & 31;
    if (lane == 0) { red[warp] = s; red[warp + 4] = s2; }
    __syncthreads();
    s = red[0] + red[1] + red[2] + red[3];
    s2 = red[4] + red[5] + red[6] + red[7];
    float mean = s * (1.f / H_);
    float var = s2 * (1.f / H_) - mean * mean;
    float rstd = rsqrtf(var + 1e-5f);
#pragma unroll
    for (int i = 0; i < 8; i++) {
        int idx = tid + i * 128;
        g_RX[base + idx] = (v[i] - mean) * rstd * gamma[idx] + beta[idx];
    }
}

__global__ void init_kernel() {
    int i = blockIdx.x * blockDim.x + threadIdx.x;
    if (i < 2 * B_ * H_) g_H[i] = 0.f;
    if (i == 0) { g_count = 0; *((unsigned*)&g_gen) = 0; }
}

// ---------------- launch ----------------
extern "C" void kernel_launch(void* const* d_in, const int* in_sizes, int n_in,
                              void* d_out, int out_size)
{
    const float* x     = (const float*)d_in[0];
    const float* Wir   = (const float*)d_in[1];
    const float* bir   = (const float*)d_in[2];
    const float* Whr   = (const float*)d_in[3];
    const float* bhr   = (const float*)d_in[4];
    const float* Wiz   = (const float*)d_in[5];
    const float* biz   = (const float*)d_in[6];
    const float* Whz   = (const float*)d_in[7];
    const float* bhz   = (const float*)d_in[8];
    const float* Win   = (const float*)d_in[9];
    const float* bin_  = (const float*)d_in[10];
    const float* Whn   = (const float*)d_in[11];
    const float* bhn   = (const float*)d_in[12];
    const float* Wskip = (const float*)d_in[13];
    const float* bskip = (const float*)d_in[14];
    const float* gamma = (const float*)d_in[15];
    const float* beta  = (const float*)d_in[16];
    const float* Wout  = (const float*)d_in[17];
    const float* bout  = (const float*)d_in[18];
    float* out = (float*)d_out;

    cudaFuncSetAttribute(gru_persistent, cudaFuncAttributeMaxDynamicSharedMemorySize,
                         SMEM_REC_BYTES);

    // Phase 1: input projections (K=I=512), remap m=b*T+t -> [t][b][h]
    dim3 gin(H_ / 64, (B_ * T_) / 128);
    gemm_tn_tf32<<<gin, 256>>>(x, Wir, bir, nullptr, 0, I_, 10, B_, H_);
    gemm_tn_tf32<<<gin, 256>>>(x, Wiz, biz, nullptr, 1, I_, 10, B_, H_);
    gemm_tn_tf32<<<gin, 256>>>(x, Win, bin_, nullptr, 2, I_, 10, B_, H_);

    // Phase 2: recurrence — ONE persistent kernel (software grid barrier; 1 CTA/SM)
    init_kernel<<<(2 * B_ * H_ + 255) / 256, 256>>>();
    gru_persistent<<<NCTA_REC, 256, SMEM_REC_BYTES>>>(Whr, Whz, Whn, bhr, bhz, bhn);

    // Phase 2b: skip projection into g_ZX (dead after recurrence)
    gemm_tn_tf32<<<gin, 256>>>(x, Wskip, bskip, nullptr, 1, I_, 10, B_, H_);

    // Phase 3: LayerNorm -> g_RX
    ln_kernel<<<T_ * B_, 128>>>(gamma, beta);

    // Phase 4: output GEMM (K=H=1024), A=g_RX [t][b][h], m=t*B+b -> out[b][t][o]
    dim3 gout(O_ / 64, (B_ * T_) / 128);
    gemm_tn_tf32<<<gout, 256>>>(nullptr, Wout, bout, out, 4, H_, 7, T_, O_);
}

// round 6
// speedup vs baseline: 1.9921x; 1.9921x over previous
#include <cuda_runtime.h>
#include <cstdint>

#define B_ 128
#define T_ 1024
#define I_ 512
#define H_ 1024
#define O_ 512
#define NCTA_REC 128   // 2 batch-halves x 64 column-slices; 1 CTA/SM -> all co-resident

// ---------------- scratch (device globals; keep total well under 2GB: nvcc emits
// host shadow symbols and an oversized .bss breaks the x86-64 link) ----------------
__device__ float g_RX[T_ * B_ * H_];     // [t][b][h] rx ; later LN output
__device__ float g_ZX[T_ * B_ * H_];     // [t][b][h] zx ; later skip projection
__device__ float g_NX[T_ * B_ * H_];     // [t][b][h] nx ; overwritten in-place with h_t
__device__ unsigned g_Htf[2 * B_ * H_];  // ping-pong hidden state, TF32 bits
__device__ volatile unsigned g_gen;      // grid barrier generation
__device__ unsigned g_count;             // grid barrier arrival counter

// ---------------- helpers ----------------
__device__ __forceinline__ unsigned f2tf32(float x) {
    unsigned r;
    asm("cvt.rna.tf32.f32 %0, %1;" : "=r"(r) : "f"(x));
    return r;
}

__device__ __forceinline__ void mma_tf32(float c[4], const unsigned a[4], const unsigned b[2]) {
    asm volatile(
        "mma.sync.aligned.m16n8k8.row.col.f32.tf32.tf32.f32 "
        "{%0,%1,%2,%3},{%4,%5,%6,%7},{%8,%9},{%0,%1,%2,%3};"
        : "+f"(c[0]), "+f"(c[1]), "+f"(c[2]), "+f"(c[3])
        : "r"(a[0]), "r"(a[1]), "r"(a[2]), "r"(a[3]), "r"(b[0]), "r"(b[1]));
}

__device__ __forceinline__ void cp16(unsigned* smem_dst, const unsigned* gsrc) {
    unsigned sa = (unsigned)__cvta_generic_to_shared(smem_dst);
    asm volatile("cp.async.cg.shared.global [%0], [%1], 16;" :: "r"(sa), "l"(gsrc));
}
__device__ __forceinline__ void cp_commit() {
    asm volatile("cp.async.commit_group;");
}
__device__ __forceinline__ void cp_wait1() {
    asm volatile("cp.async.wait_group 1;");
}

__device__ __forceinline__ void grid_barrier() {
    __syncthreads();
    if (threadIdx.x == 0) {
        __threadfence();
        unsigned old = g_gen;
        if (atomicAdd(&g_count, 1) == NCTA_REC - 1) {
            g_count = 0;
            __threadfence();
            g_gen = old + 1;
        } else {
            while (g_gen == old) { __nanosleep(64); }
        }
    }
    __syncthreads();
}

// ---------------- generic TN GEMM:  C = A(MxK, row-major) * W(NxK, row-major)^T + bias ----------------
// A source: Aext if non-null, else g_RX.
// C dest (c_sel): 0=g_RX 1=g_ZX 2=g_NX 4=Cext.
// Output remap: element (m,n) -> C[ ((m % 2^p_shift) * Q + (m >> p_shift)) * ldo + n ]
__global__ __launch_bounds__(256) void gemm_tn_tf32(
    const float* __restrict__ Aext, const float* __restrict__ W,
    const float* __restrict__ bias, float* __restrict__ Cext,
    int c_sel, int K, int p_shift, int Q, int ldo)
{
    __shared__ unsigned As[128][36];
    __shared__ unsigned Bs[64][36];

    const float* A = Aext ? Aext : g_RX;
    float* Cout;
    switch (c_sel) {
        case 0: Cout = g_RX; break;
        case 1: Cout = g_ZX; break;
        case 2: Cout = g_NX; break;
        default: Cout = Cext; break;
    }

    const int tid  = threadIdx.x;
    const int m0   = blockIdx.y * 128;
    const int n0   = blockIdx.x * 64;
    const int warp = tid >> 5, lane = tid & 31;
    const int g    = lane >> 2, tig = lane & 3;
    const int wM   = warp & 3, wN = warp >> 2;

    float acc[2][4][4];
#pragma unroll
    for (int mt = 0; mt < 2; mt++)
#pragma unroll
        for (int nt = 0; nt < 4; nt++)
#pragma unroll
            for (int r = 0; r < 4; r++) acc[mt][nt][r] = 0.f;

    for (int kt = 0; kt < K; kt += 32) {
#pragma unroll
        for (int j = 0; j < 4; j++) {
            int f = tid + j * 256;
            int row = f >> 3, c4 = (f & 7) * 4;
            float4 v = *reinterpret_cast<const float4*>(&A[(size_t)(m0 + row) * K + kt + c4]);
            As[row][c4 + 0] = f2tf32(v.x); As[row][c4 + 1] = f2tf32(v.y);
            As[row][c4 + 2] = f2tf32(v.z); As[row][c4 + 3] = f2tf32(v.w);
        }
#pragma unroll
        for (int j = 0; j < 2; j++) {
            int f = tid + j * 256;
            int row = f >> 3, c4 = (f & 7) * 4;
            float4 v = *reinterpret_cast<const float4*>(&W[(size_t)(n0 + row) * K + kt + c4]);
            Bs[row][c4 + 0] = f2tf32(v.x); Bs[row][c4 + 1] = f2tf32(v.y);
            Bs[row][c4 + 2] = f2tf32(v.z); Bs[row][c4 + 3] = f2tf32(v.w);
        }
        __syncthreads();

#pragma unroll
        for (int ks = 0; ks < 4; ks++) {
            const int kk = ks * 8;
            unsigned af[2][4], bf[4][2];
#pragma unroll
            for (int mt = 0; mt < 2; mt++) {
                int r0 = wM * 32 + mt * 16 + g;
                af[mt][0] = As[r0][kk + tig];
                af[mt][1] = As[r0 + 8][kk + tig];
                af[mt][2] = As[r0][kk + tig + 4];
                af[mt][3] = As[r0 + 8][kk + tig + 4];
            }
#pragma unroll
            for (int nt = 0; nt < 4; nt++) {
                int r0 = wN * 32 + nt * 8 + g;
                bf[nt][0] = Bs[r0][kk + tig];
                bf[nt][1] = Bs[r0][kk + tig + 4];
            }
#pragma unroll
            for (int mt = 0; mt < 2; mt++)
#pragma unroll
                for (int nt = 0; nt < 4; nt++) mma_tf32(acc[mt][nt], af[mt], bf[nt]);
        }
        __syncthreads();
    }

    const int Pm1 = (1 << p_shift) - 1;
#pragma unroll
    for (int mt = 0; mt < 2; mt++)
#pragma unroll
        for (int nt = 0; nt < 4; nt++)
#pragma unroll
            for (int r = 0; r < 4; r++) {
                int row = m0 + wM * 32 + mt * 16 + g + ((r >> 1) << 3);
                int col = n0 + wN * 32 + nt * 8 + 2 * tig + (r & 1);
                size_t oidx = ((size_t)((row & Pm1) * Q + (row >> p_shift))) * ldo + col;
                Cout[oidx] = acc[mt][nt][r] + bias[col];
            }
}

// ---------------- persistent GRU recurrence ----------------
// 128 CTAs = (bhalf 0..1) x (64 col slices of 16). Weights resident in SMEM (tf32).
// h stored ping-pong in GLOBAL as TF32 bits; staged via cp.async 3-stage pipeline.
// Per-thread h kept in registers across steps (same thread owns same (row,col)).
#define WSTRIDE 1028
#define SMEM_REC_BYTES ((3 * 16 * WSTRIDE + 3 * 64 * 36) * 4)

__global__ __launch_bounds__(256) void gru_persistent(
    const float* __restrict__ Whr, const float* __restrict__ Whz, const float* __restrict__ Whn,
    const float* __restrict__ bhr, const float* __restrict__ bhz, const float* __restrict__ bhn)
{
    extern __shared__ unsigned smem[];
    unsigned* Wp  = smem;                       // [3][16][WSTRIDE]
    unsigned* Hst = smem + 3 * 16 * WSTRIDE;    // [3][64][36] cp.async staging

    const int tid  = threadIdx.x, warp = tid >> 5, lane = tid & 31;
    const int g    = lane >> 2, tig = lane & 3;
    const int wM   = warp & 3, wN = warp >> 2;   // 4 m-warps x 2 n-warps
    const int bhalf = blockIdx.x >> 6;           // 0..1 (64 batch rows each)
    const int nbase = (blockIdx.x & 63) * 16;    // 16-column slice

    // one-time: stage this CTA's weight slice into SMEM (tf32)
    for (int idx = tid; idx < 3 * 16 * 256; idx += 256) {
        int q = idx >> 12;
        int rem = idx & 4095;
        int c = rem >> 8;
        int k4 = (rem & 255) * 4;
        const float* wsrc = (q == 0) ? Whr : (q == 1) ? Whz : Whn;
        float4 v = *reinterpret_cast<const float4*>(&wsrc[(size_t)(nbase + c) * H_ + k4]);
        unsigned* d = Wp + (q * 16 + c) * WSTRIDE + k4;
        d[0] = f2tf32(v.x); d[1] = f2tf32(v.y); d[2] = f2tf32(v.z); d[3] = f2tf32(v.w);
    }
    __syncthreads();

    // per-thread output coordinates (4 outputs: 2 rows x 2 cols)
    int orow[4], ocol[4];
    float b_r[4], b_z[4], b_n[4], hreg[4];
#pragma unroll
    for (int r = 0; r < 4; r++) {
        orow[r] = bhalf * 64 + wM * 16 + g + ((r >> 1) << 3);
        ocol[r] = nbase + wN * 8 + 2 * tig + (r & 1);
        b_r[r] = bhr[ocol[r]]; b_z[r] = bhz[ocol[r]]; b_n[r] = bhn[ocol[r]];
        hreg[r] = 0.f;  // h0 = 0
    }

    for (int t = 0; t < T_; t++) {
        const unsigned* hsrc = g_Htf + (size_t)(t & 1) * (B_ * H_);
        unsigned* hdst = g_Htf + (size_t)((t + 1) & 1) * (B_ * H_);

        // prefetch gate inputs for this step (hidden behind the whole chunk loop)
        float rxv[4], zxv[4], nxv[4];
#pragma unroll
        for (int r = 0; r < 4; r++) {
            size_t gi = (size_t)t * (B_ * H_) + (size_t)orow[r] * H_ + ocol[r];
            rxv[r] = __ldcg(&g_RX[gi]);
            zxv[r] = __ldcg(&g_ZX[gi]);
            nxv[r] = __ldcg(&g_NX[gi]);
        }

        auto issue_chunk = [&](int c) {
            int buf = c % 3;
#pragma unroll
            for (int j = 0; j < 2; j++) {
                int f = tid + j * 256;
                int row = f >> 3, c4 = (f & 7) * 4;
                cp16(Hst + (buf * 64 + row) * 36 + c4,
                     hsrc + (size_t)(bhalf * 64 + row) * H_ + c * 32 + c4);
            }
        };

        float acc[3][4];
#pragma unroll
        for (int q = 0; q < 3; q++)
#pragma unroll
            for (int r = 0; r < 4; r++) acc[q][r] = 0.f;

        issue_chunk(0); cp_commit();
        issue_chunk(1); cp_commit();

        for (int cch = 0; cch < 32; cch++) {
            cp_wait1();
            __syncthreads();
            if (cch + 2 < 32) issue_chunk(cch + 2);
            cp_commit();

            const int kt = cch * 32;
            const unsigned* hb = Hst + (cch % 3) * 64 * 36;
#pragma unroll
            for (int ks = 0; ks < 4; ks++) {
                const int kk = ks * 8;
                unsigned af[4];
                const int r0 = wM * 16 + g;
                af[0] = hb[(r0)     * 36 + kk + tig];
                af[1] = hb[(r0 + 8) * 36 + kk + tig];
                af[2] = hb[(r0)     * 36 + kk + tig + 4];
                af[3] = hb[(r0 + 8) * 36 + kk + tig + 4];
#pragma unroll
                for (int q = 0; q < 3; q++) {
                    const unsigned* wrow = Wp + (q * 16 + wN * 8 + g) * WSTRIDE + kt + kk;
                    unsigned bf[2] = {wrow[tig], wrow[tig + 4]};
                    mma_tf32(acc[q], af, bf);
                }
            }
        }

        // epilogue: gates + h update (h carried in registers)
#pragma unroll
        for (int r = 0; r < 4; r++) {
            size_t gi = (size_t)t * (B_ * H_) + (size_t)orow[r] * H_ + ocol[r];
            float rp = acc[0][r] + b_r[r] + rxv[r];
            float zp = acc[1][r] + b_z[r] + zxv[r];
            float rr = 1.f / (1.f + __expf(-rp));
            float zz = 1.f / (1.f + __expf(-zp));
            float nn = tanhf(nxv[r] + rr * (acc[2][r] + b_n[r]));
            float hn = fmaf(zz, hreg[r] - nn, nn);
            hreg[r] = hn;
            hdst[(size_t)orow[r] * H_ + ocol[r]] = f2tf32(hn);
            g_NX[gi] = hn;  // HS shares the NX buffer
        }

        grid_barrier();
    }
}

// ---------------- LayerNorm over H of (g_NX=hs + g_ZX=skip), writes into g_RX ----------------
__global__ __launch_bounds__(128) void ln_kernel(
    const float* __restrict__ gamma, const float* __restrict__ beta)
{
    __shared__ float red[8];
    const size_t base = (size_t)blockIdx.x * H_;
    const int tid = threadIdx.x;
    float v[8], s = 0.f, s2 = 0.f;
#pragma unroll
    for (int i = 0; i < 8; i++) {
        int idx = tid + i * 128;
        float c = g_NX[base + idx] + g_ZX[base + idx];
        v[i] = c; s += c; s2 += c * c;
    }
#pragma unroll
    for (int o = 16; o > 0; o >>= 1) {
        s += __shfl_xor_sync(0xFFFFFFFFu, s, o);
        s2 += __shfl_xor_sync(0xFFFFFFFFu, s2, o);
    }
    int warp = tid >> 5, lane = tid & 31;
    if (lane == 0) { red[warp] = s; red[warp + 4] = s2; }
    __syncthreads();
    s = red[0] + red[1] + red[2] + red[3];
    s2 = red[4] + red[5] + red[6] + red[7];
    float mean = s * (1.f / H_);
    float var = s2 * (1.f / H_) - mean * mean;
    float rstd = rsqrtf(var + 1e-5f);
#pragma unroll
    for (int i = 0; i < 8; i++) {
        int idx = tid + i * 128;
        g_RX[base + idx] = (v[i] - mean) * rstd * gamma[idx] + beta[idx];
    }
}

__global__ void init_kernel() {
    int i = blockIdx.x * blockDim.x + threadIdx.x;
    if (i < 2 * B_ * H_) g_Htf[i] = 0u;  // 0 bits == 0.0f in tf32
    if (i == 0) { g_count = 0; *((unsigned*)&g_gen) = 0; }
}

// ---------------- launch ----------------
extern "C" void kernel_launch(void* const* d_in, const int* in_sizes, int n_in,
                              void* d_out, int out_size)
{
    const float* x     = (const float*)d_in[0];
    const float* Wir   = (const float*)d_in[1];
    const float* bir   = (const float*)d_in[2];
    const float* Whr   = (const float*)d_in[3];
    const float* bhr   = (const float*)d_in[4];
    const float* Wiz   = (const float*)d_in[5];
    const float* biz   = (const float*)d_in[6];
    const float* Whz   = (const float*)d_in[7];
    const float* bhz   = (const float*)d_in[8];
    const float* Win   = (const float*)d_in[9];
    const float* bin_  = (const float*)d_in[10];
    const float* Whn   = (const float*)d_in[11];
    const float* bhn   = (const float*)d_in[12];
    const float* Wskip = (const float*)d_in[13];
    const float* bskip = (const float*)d_in[14];
    const float* gamma = (const float*)d_in[15];
    const float* beta  = (const float*)d_in[16];
    const float* Wout  = (const float*)d_in[17];
    const float* bout  = (const float*)d_in[18];
    float* out = (float*)d_out;

    cudaFuncSetAttribute(gru_persistent, cudaFuncAttributeMaxDynamicSharedMemorySize,
                         SMEM_REC_BYTES);

    // Phase 1: input projections (K=I=512), remap m=b*T+t -> [t][b][h]
    dim3 gin(H_ / 64, (B_ * T_) / 128);
    gemm_tn_tf32<<<gin, 256>>>(x, Wir, bir, nullptr, 0, I_, 10, B_, H_);
    gemm_tn_tf32<<<gin, 256>>>(x, Wiz, biz, nullptr, 1, I_, 10, B_, H_);
    gemm_tn_tf32<<<gin, 256>>>(x, Win, bin_, nullptr, 2, I_, 10, B_, H_);

    // Phase 2: recurrence — ONE persistent kernel (software grid barrier; 1 CTA/SM)
    init_kernel<<<(2 * B_ * H_ + 255) / 256, 256>>>();
    gru_persistent<<<NCTA_REC, 256, SMEM_REC_BYTES>>>(Whr, Whz, Whn, bhr, bhz, bhn);

    // Phase 2b: skip projection into g_ZX (dead after recurrence)
    gemm_tn_tf32<<<gin, 256>>>(x, Wskip, bskip, nullptr, 1, I_, 10, B_, H_);

    // Phase 3: LayerNorm -> g_RX
    ln_kernel<<<T_ * B_, 128>>>(gamma, beta);

    // Phase 4: output GEMM (K=H=1024), A=g_RX [t][b][h], m=t*B+b -> out[b][t][o]
    dim3 gout(O_ / 64, (B_ * T_) / 128);
    gemm_tn_tf32<<<gout, 256>>>(nullptr, Wout, bout, out, 4, H_, 7, T_, O_);
}